// round 7
// baseline (speedup 1.0000x reference)
#include <cuda_runtime.h>

// ProdAt: x [16384, 8192] fp32 -> out [16384, 128] fp32
// out[seg] = prod of 64 contiguous floats.
//
// Best-measured geometry (R5):
//   8 lanes per segment; each lane loads f4[sub] and f4[sub+8] (each LDG.128
//   by an 8-lane group covers one full 128B line -> perfect coalescing).
//   Each thread handles 2 ADJACENT segments -> 4 independent LDG.128 (MLP=4);
//   sub==0 lanes store packed float2 (STG.64). 512-thread blocks.
// New in R7: loads use ld.global.nc.L1::evict_first.L2::256B — the 256B L2
//   promotion hint lets LTS service adjacent 128B lines as one 256B access,
//   halving L2 request count on the read stream.

static constexpr long long N_SEGMENTS_TOTAL = 16384LL * 128LL;  // 2,097,152

__device__ __forceinline__ float4 ldg_stream_256(const float4* p) {
    float4 v;
    asm volatile("ld.global.nc.L1::evict_first.L2::256B.v4.f32 {%0,%1,%2,%3}, [%4];"
                 : "=f"(v.x), "=f"(v.y), "=f"(v.z), "=f"(v.w)
                 : "l"(p));
    return v;
}

__device__ __forceinline__ float prod4(float4 v) {
    return (v.x * v.y) * (v.z * v.w);
}

__global__ void __launch_bounds__(512) prodat_kernel(
    const float* __restrict__ x, float* __restrict__ out)
{
    const long long warp_id =
        (long long)blockIdx.x * (blockDim.x >> 5) + (threadIdx.x >> 5);
    const int lane = threadIdx.x & 31;

    const int g   = lane >> 3;   // 0..3 : segment-pair group within warp
    const int sub = lane & 7;    // 0..7 : float4 slot within segment half

    // warp covers 8 consecutive segments [warp_id*8, warp_id*8+8)
    // this thread: adjacent segments 2g and 2g+1
    const long long seg0 = warp_id * 8 + 2 * g;
    const long long seg1 = seg0 + 1;

    const float4* x4 = reinterpret_cast<const float4*>(x);

    // front-batch 4 independent loads (MLP = 4), 256B L2 promotion
    const float4 a0 = ldg_stream_256(x4 + seg0 * 16 + sub);
    const float4 b0 = ldg_stream_256(x4 + seg0 * 16 + 8 + sub);
    const float4 a1 = ldg_stream_256(x4 + seg1 * 16 + sub);
    const float4 b1 = ldg_stream_256(x4 + seg1 * 16 + 8 + sub);

    float p0 = prod4(a0) * prod4(b0);
    float p1 = prod4(a1) * prod4(b1);

    // two independent 3-step reductions over the 8-lane group (pipelined)
    #pragma unroll
    for (int off = 4; off > 0; off >>= 1) {
        p0 *= __shfl_xor_sync(0xffffffffu, p0, off);
        p1 *= __shfl_xor_sync(0xffffffffu, p1, off);
    }

    if (sub == 0) {
        // packed 8B store of two adjacent segment results (STG.64)
        reinterpret_cast<float2*>(out)[seg0 >> 1] = make_float2(p0, p1);
    }
}

extern "C" void kernel_launch(void* const* d_in, const int* in_sizes, int n_in,
                              void* d_out, int out_size)
{
    const float* x = (const float*)d_in[0];
    float* out = (float*)d_out;

    // 512 threads = 16 warps = 128 segments per block
    const int threads = 512;
    const long long blocks = N_SEGMENTS_TOTAL / 128;  // 16384, exact

    prodat_kernel<<<(unsigned)blocks, threads>>>(x, out);
}

// round 8
// speedup vs baseline: 1.0028x; 1.0028x over previous
#include <cuda_runtime.h>

// ProdAt: x [16384, 8192] fp32 -> out [16384, 128] fp32
// out[seg] = prod of 64 contiguous floats.
//
// R8: Blackwell 256-bit loads (ld.global.nc.v8.f32 -> LDG.E.256).
//   8 lanes per segment; each lane loads ONE 32B v8 chunk, so a single
//   LDG.256 by an 8-lane group covers an entire 256B segment (perfect
//   coalescing, half the LDG instructions / L1tex queue slots of LDG.128).
//   Each thread handles 2 ADJACENT segments -> 2 front-batched LDG.256
//   (64B/thread in flight, same as best R5 config). 3-step shfl_xor
//   reduce over the 8-lane group; sub==0 lanes store packed float2.

static constexpr long long N_SEGMENTS_TOTAL = 16384LL * 128LL;  // 2,097,152

struct f8 { float v[8]; };

__device__ __forceinline__ f8 ldg_v8(const float* p) {
    f8 r;
    asm volatile(
        "ld.global.nc.L1::evict_first.v8.f32 "
        "{%0,%1,%2,%3,%4,%5,%6,%7}, [%8];"
        : "=f"(r.v[0]), "=f"(r.v[1]), "=f"(r.v[2]), "=f"(r.v[3]),
          "=f"(r.v[4]), "=f"(r.v[5]), "=f"(r.v[6]), "=f"(r.v[7])
        : "l"(p));
    return r;
}

__device__ __forceinline__ float prod8(const f8& a) {
    return ((a.v[0] * a.v[1]) * (a.v[2] * a.v[3])) *
           ((a.v[4] * a.v[5]) * (a.v[6] * a.v[7]));
}

__global__ void __launch_bounds__(512) prodat_kernel(
    const float* __restrict__ x, float* __restrict__ out)
{
    const long long warp_id =
        (long long)blockIdx.x * (blockDim.x >> 5) + (threadIdx.x >> 5);
    const int lane = threadIdx.x & 31;

    const int g   = lane >> 3;   // 0..3 : segment-pair group within warp
    const int sub = lane & 7;    // 0..7 : 32B slot within segment

    // warp covers 8 consecutive segments [warp_id*8, warp_id*8+8)
    // this thread: adjacent segments 2g and 2g+1
    const long long seg0 = warp_id * 8 + 2 * g;
    const long long seg1 = seg0 + 1;

    // front-batch 2 independent 256-bit loads (64B/thread in flight)
    const f8 a0 = ldg_v8(x + seg0 * 64 + sub * 8);
    const f8 a1 = ldg_v8(x + seg1 * 64 + sub * 8);

    float p0 = prod8(a0);
    float p1 = prod8(a1);

    // two independent 3-step reductions over the 8-lane group (pipelined)
    #pragma unroll
    for (int off = 4; off > 0; off >>= 1) {
        p0 *= __shfl_xor_sync(0xffffffffu, p0, off);
        p1 *= __shfl_xor_sync(0xffffffffu, p1, off);
    }

    if (sub == 0) {
        // packed 8B store of two adjacent segment results (STG.64)
        reinterpret_cast<float2*>(out)[seg0 >> 1] = make_float2(p0, p1);
    }
}

extern "C" void kernel_launch(void* const* d_in, const int* in_sizes, int n_in,
                              void* d_out, int out_size)
{
    const float* x = (const float*)d_in[0];
    float* out = (float*)d_out;

    // 512 threads = 16 warps = 128 segments per block
    const int threads = 512;
    const long long blocks = N_SEGMENTS_TOTAL / 128;  // 16384, exact

    prodat_kernel<<<(unsigned)blocks, threads>>>(x, out);
}